// round 3
// baseline (speedup 1.0000x reference)
#include <cuda_runtime.h>

// Problem constants
#define BB 32
#define TT 24
#define NN 325
#define DD 64
#define NHEAD 8
#define DHEAD 8

#define NB 6                  // nodes per CTA
#define MROWS (NB * TT)       // 144 rows per CTA tile
#define NTILES ((NN + NB - 1) / NB)   // 55
#define NTHREADS 384

#define ST 68                 // padded stride for Q/K/V (floats)
#define STD 136               // duplicated-A stride (floats): x0,x0,x1,x1,...

// shared memory layout (floats)
#define XD_OFF 0                              // 144*136 = 19584 (dup A: X -> O)
#define QS_OFF 19584                          // 144*68 = 9792
#define KS_OFF (QS_OFF + MROWS * ST)          // 29376
#define VS_OFF (KS_OFF + MROWS * ST)          // 39168
#define W0_OFF (VS_OFF + MROWS * ST)          // 48960
#define W1_OFF (W0_OFF + 4096)                // 53056
#define HD_OFF QS_OFF                         // H-dup reuses Q+K regions (2*9792 = 19584)
#define SMEM_FLOATS (W1_OFF + 4096)           // 57152
#define SMEM_BYTES (SMEM_FLOATS * 4)          // 228608 B

typedef unsigned long long ull;

__device__ __forceinline__ ull ffma2(ull a, ull b, ull c) {
    ull d;
    asm("fma.rn.f32x2 %0, %1, %2, %3;" : "=l"(d) : "l"(a), "l"(b), "l"(c));
    return d;
}
__device__ __forceinline__ float2 unpack2(ull v) {
    float2 r;
    asm("mov.b64 {%0, %1}, %2;" : "=f"(r.x), "=f"(r.y) : "l"(v));
    return r;
}

// ---------------------------------------------------------------------------
// Stage one 64x64 weight matrix into a shared slot (coalesced float4).
// ---------------------------------------------------------------------------
__device__ __forceinline__ void load_weight(float* __restrict__ Wsm,
                                            const float* __restrict__ Wg,
                                            int tid) {
#pragma unroll
    for (int i = 0; i < 3; ++i) {
        int idx = tid + i * NTHREADS;      // 1024 float4 total
        if (idx < 1024)
            *(float4*)(Wsm + idx * 4) = *(const float4*)(Wg + idx * 4);
    }
}

// ---------------------------------------------------------------------------
// GEMM core: A in duplicated layout (STD), W in smem (stride 64).
// Thread tile 6 rows x 4 cols; 24 row-groups x 16 col-groups = 384 threads.
// FFMA2 throughout; A operands come pre-packed {x,x} from the dup layout.
// ---------------------------------------------------------------------------
__device__ __forceinline__ void gemm_core(const float* __restrict__ Ad,
                                          const float* __restrict__ Wsm,
                                          ull acc[6][2], int r0, int c0) {
#pragma unroll
    for (int i = 0; i < 6; ++i) { acc[i][0] = 0ull; acc[i][1] = 0ull; }

#pragma unroll 2
    for (int kk = 0; kk < 64; kk += 4) {
        ulonglong2 w[4];
#pragma unroll
        for (int k = 0; k < 4; ++k)
            w[k] = *(const ulonglong2*)(Wsm + (kk + k) * DD + c0);
#pragma unroll
        for (int i = 0; i < 6; ++i) {
            const float* arow = Ad + (r0 + i) * STD + 2 * kk;
            ulonglong2 a0 = *(const ulonglong2*)(arow);      // {k,k},{k+1,k+1}
            ulonglong2 a1 = *(const ulonglong2*)(arow + 4);  // {k+2,k+2},{k+3,k+3}
            acc[i][0] = ffma2(a0.x, w[0].x, acc[i][0]);
            acc[i][1] = ffma2(a0.x, w[0].y, acc[i][1]);
            acc[i][0] = ffma2(a0.y, w[1].x, acc[i][0]);
            acc[i][1] = ffma2(a0.y, w[1].y, acc[i][1]);
            acc[i][0] = ffma2(a1.x, w[2].x, acc[i][0]);
            acc[i][1] = ffma2(a1.x, w[2].y, acc[i][1]);
            acc[i][0] = ffma2(a1.y, w[3].x, acc[i][0]);
            acc[i][1] = ffma2(a1.y, w[3].y, acc[i][1]);
        }
    }
}

// Epilogue -> padded ST buffer (Q/K/V), bias + ReLU.
__device__ __forceinline__ void gemm_to_pad(const float* __restrict__ Ad,
                                            const float* __restrict__ Wsm,
                                            const float* __restrict__ bias,
                                            float* __restrict__ outs, int tid) {
    const int r0 = (tid >> 4) * 6;
    const int c0 = (tid & 15) * 4;
    ull acc[6][2];
    gemm_core(Ad, Wsm, acc, r0, c0);
    float4 bb = *(const float4*)(bias + c0);
#pragma unroll
    for (int i = 0; i < 6; ++i) {
        float2 p0 = unpack2(acc[i][0]);
        float2 p1 = unpack2(acc[i][1]);
        float4 r;
        r.x = fmaxf(p0.x + bb.x, 0.f);
        r.y = fmaxf(p0.y + bb.y, 0.f);
        r.z = fmaxf(p1.x + bb.z, 0.f);
        r.w = fmaxf(p1.y + bb.w, 0.f);
        *(float4*)(outs + (r0 + i) * ST + c0) = r;
    }
}

// Epilogue -> duplicated STD buffer (FC1 hidden), bias + ReLU.
__device__ __forceinline__ void gemm_to_dup(const float* __restrict__ Ad,
                                            const float* __restrict__ Wsm,
                                            const float* __restrict__ bias,
                                            float* __restrict__ outd, int tid) {
    const int r0 = (tid >> 4) * 6;
    const int c0 = (tid & 15) * 4;
    ull acc[6][2];
    gemm_core(Ad, Wsm, acc, r0, c0);
    float4 bb = *(const float4*)(bias + c0);
#pragma unroll
    for (int i = 0; i < 6; ++i) {
        float2 p0 = unpack2(acc[i][0]);
        float2 p1 = unpack2(acc[i][1]);
        float rx = fmaxf(p0.x + bb.x, 0.f);
        float ry = fmaxf(p0.y + bb.y, 0.f);
        float rz = fmaxf(p1.x + bb.z, 0.f);
        float rw = fmaxf(p1.y + bb.w, 0.f);
        float* dst = outd + (r0 + i) * STD + 2 * c0;
        *(float4*)(dst) = make_float4(rx, rx, ry, ry);
        *(float4*)(dst + 4) = make_float4(rz, rz, rw, rw);
    }
}

// Epilogue -> global Y (final layer), bias, no ReLU, node guard.
__device__ __forceinline__ void gemm_to_global(const float* __restrict__ Ad,
                                               const float* __restrict__ Wsm,
                                               const float* __restrict__ bias,
                                               float* __restrict__ Y,
                                               int b, int n0, int tid) {
    const int r0 = (tid >> 4) * 6;
    const int c0 = (tid & 15) * 4;
    ull acc[6][2];
    gemm_core(Ad, Wsm, acc, r0, c0);
    float4 bb = *(const float4*)(bias + c0);
#pragma unroll
    for (int i = 0; i < 6; ++i) {
        int row = r0 + i;
        int node = row / TT;
        int t = row - node * TT;
        int n = n0 + node;
        if (n < NN) {
            float2 p0 = unpack2(acc[i][0]);
            float2 p1 = unpack2(acc[i][1]);
            float4 r = make_float4(p0.x + bb.x, p0.y + bb.y,
                                   p1.x + bb.z, p1.y + bb.w);
            *(float4*)(Y + ((size_t)(b * TT + t) * NN + n) * DD + c0) = r;
        }
    }
}

// ---------------------------------------------------------------------------
// Per-(node, t, head) attention over temporal axis (keep s >= t).
// Reads Q/K/V (ST layout), writes O in DUP layout (A operand of FC1).
// ---------------------------------------------------------------------------
__device__ __forceinline__ void attention(const float* __restrict__ Qs,
                                          const float* __restrict__ Ks,
                                          const float* __restrict__ Vs,
                                          float* __restrict__ Od,
                                          int tid) {
    const float scale = 0.3535533905932738f;  // 1/sqrt(8)
#pragma unroll 1
    for (int iter = 0; iter < NB * TT * NHEAD / NTHREADS; ++iter) {
        int task = iter * NTHREADS + tid;     // 0..1151
        int h = task & 7;
        int t = (task >> 3) % TT;
        int node = task / (TT * NHEAD);
        int base = node * TT;
        int hc = h * DHEAD;

        float4 q0 = *(const float4*)(Qs + (base + t) * ST + hc);
        float4 q1 = *(const float4*)(Qs + (base + t) * ST + hc + 4);
        q0.x *= scale; q0.y *= scale; q0.z *= scale; q0.w *= scale;
        q1.x *= scale; q1.y *= scale; q1.z *= scale; q1.w *= scale;

        float p[TT];
        float m = -1e30f;
#pragma unroll
        for (int s = 0; s < TT; ++s) {
            float4 k0 = *(const float4*)(Ks + (base + s) * ST + hc);
            float4 k1 = *(const float4*)(Ks + (base + s) * ST + hc + 4);
            float dot = q0.x * k0.x;
            dot = fmaf(q0.y, k0.y, dot);
            dot = fmaf(q0.z, k0.z, dot);
            dot = fmaf(q0.w, k0.w, dot);
            dot = fmaf(q1.x, k1.x, dot);
            dot = fmaf(q1.y, k1.y, dot);
            dot = fmaf(q1.z, k1.z, dot);
            dot = fmaf(q1.w, k1.w, dot);
            dot = (s >= t) ? dot : -1e30f;
            p[s] = dot;
            m = fmaxf(m, dot);
        }
        float sum = 0.0f;
#pragma unroll
        for (int s = 0; s < TT; ++s) {
            float e = __expf(p[s] - m);   // masked -> exactly 0
            p[s] = e;
            sum += e;
        }
        float inv = 1.0f / sum;

        float o[8] = {0, 0, 0, 0, 0, 0, 0, 0};
#pragma unroll
        for (int s = 0; s < TT; ++s) {
            float4 v0 = *(const float4*)(Vs + (base + s) * ST + hc);
            float4 v1 = *(const float4*)(Vs + (base + s) * ST + hc + 4);
            o[0] = fmaf(p[s], v0.x, o[0]);
            o[1] = fmaf(p[s], v0.y, o[1]);
            o[2] = fmaf(p[s], v0.z, o[2]);
            o[3] = fmaf(p[s], v0.w, o[3]);
            o[4] = fmaf(p[s], v1.x, o[4]);
            o[5] = fmaf(p[s], v1.y, o[5]);
            o[6] = fmaf(p[s], v1.z, o[6]);
            o[7] = fmaf(p[s], v1.w, o[7]);
        }
        float* dst = Od + (base + t) * STD + 2 * hc;
        *(float4*)(dst)      = make_float4(o[0]*inv, o[0]*inv, o[1]*inv, o[1]*inv);
        *(float4*)(dst + 4)  = make_float4(o[2]*inv, o[2]*inv, o[3]*inv, o[3]*inv);
        *(float4*)(dst + 8)  = make_float4(o[4]*inv, o[4]*inv, o[5]*inv, o[5]*inv);
        *(float4*)(dst + 12) = make_float4(o[6]*inv, o[6]*inv, o[7]*inv, o[7]*inv);
    }
}

// ---------------------------------------------------------------------------
// Fused kernel: one CTA per (batch, 6-node tile).
// ---------------------------------------------------------------------------
__global__ void __launch_bounds__(NTHREADS, 1)
temporal_attention_fused(const float* __restrict__ X,
                         const float* __restrict__ Wq, const float* __restrict__ bq,
                         const float* __restrict__ Wk, const float* __restrict__ bk,
                         const float* __restrict__ Wv, const float* __restrict__ bv,
                         const float* __restrict__ Wf1, const float* __restrict__ bf1,
                         const float* __restrict__ Wf2, const float* __restrict__ bf2,
                         float* __restrict__ Y) {
    extern __shared__ float smem[];
    float* Xd = smem + XD_OFF;   // dup-layout A: X, later attention output O
    float* Qs = smem + QS_OFF;
    float* Ks = smem + KS_OFF;
    float* Vs = smem + VS_OFF;
    float* Hd = smem + HD_OFF;   // dup-layout FC1 hidden (over Q+K regions)
    float* W0 = smem + W0_OFF;
    float* W1 = smem + W1_OFF;

    const int tid = threadIdx.x;
    const int n0 = blockIdx.x * NB;
    const int b = blockIdx.y;

    // Load X tile into dup layout; zero-fill out-of-range nodes.
#pragma unroll 2
    for (int i = tid; i < MROWS * 16; i += NTHREADS) {
        int row = i >> 4;
        int f4 = i & 15;
        int node = row / TT;
        int t = row - node * TT;
        int n = n0 + node;
        float4 v = make_float4(0.f, 0.f, 0.f, 0.f);
        if (n < NN)
            v = *(const float4*)(X + ((size_t)(b * TT + t) * NN + n) * DD + f4 * 4);
        float* dst = Xd + row * STD + 8 * f4;
        *(float4*)(dst)     = make_float4(v.x, v.x, v.y, v.y);
        *(float4*)(dst + 4) = make_float4(v.z, v.z, v.w, v.w);
    }
    load_weight(W0, Wq, tid);
    __syncthreads();

    load_weight(W1, Wk, tid);                 // overlap with Q GEMM
    gemm_to_pad(Xd, W0, bq, Qs, tid);         // q = relu(X@Wq + bq)
    __syncthreads();

    load_weight(W0, Wv, tid);
    gemm_to_pad(Xd, W1, bk, Ks, tid);         // k
    __syncthreads();

    load_weight(W1, Wf1, tid);
    gemm_to_pad(Xd, W0, bv, Vs, tid);         // v
    __syncthreads();

    attention(Qs, Ks, Vs, Xd, tid);           // O (dup) overwrites Xd
    __syncthreads();

    load_weight(W0, Wf2, tid);
    gemm_to_dup(Xd, W1, bf1, Hd, tid);        // h = relu(O@Wf1 + bf1) (dup, over Q+K)
    __syncthreads();

    gemm_to_global(Hd, W0, bf2, Y, b, n0, tid);  // y = h@Wf2 + bf2
}

// ---------------------------------------------------------------------------
// kernel_launch: inputs per metadata order:
// 0=X 1=STE(unused) 2=Wq 3=bq 4=Wk 5=bk 6=Wv 7=bv 8=Wf1 9=bf1 10=Wf2 11=bf2
// ---------------------------------------------------------------------------
extern "C" void kernel_launch(void* const* d_in, const int* in_sizes, int n_in,
                              void* d_out, int out_size) {
    const float* X   = (const float*)d_in[0];
    const float* Wq  = (const float*)d_in[2];
    const float* bq  = (const float*)d_in[3];
    const float* Wk  = (const float*)d_in[4];
    const float* bk  = (const float*)d_in[5];
    const float* Wv  = (const float*)d_in[6];
    const float* bv  = (const float*)d_in[7];
    const float* Wf1 = (const float*)d_in[8];
    const float* bf1 = (const float*)d_in[9];
    const float* Wf2 = (const float*)d_in[10];
    const float* bf2 = (const float*)d_in[11];
    float* Y = (float*)d_out;

    cudaFuncSetAttribute(temporal_attention_fused,
                         cudaFuncAttributeMaxDynamicSharedMemorySize, SMEM_BYTES);

    dim3 grid(NTILES, BB);
    temporal_attention_fused<<<grid, NTHREADS, SMEM_BYTES>>>(
        X, Wq, bq, Wk, bk, Wv, bv, Wf1, bf1, Wf2, bf2, Y);
}

// round 4
// speedup vs baseline: 1.0254x; 1.0254x over previous
#include <cuda_runtime.h>

// Problem constants
#define BB 32
#define TT 24
#define NN 325
#define DD 64
#define NHEAD 8
#define DHEAD 8

#define NB 8                  // nodes per CTA
#define MROWS (NB * TT)       // 192 rows
#define NTILES ((NN + NB - 1) / NB)   // 41
#define NTHREADS 384

// smem float offsets
#define XB_OFF 0                      // 192*64 = 12288 (X -> attention O)
#define QB_OFF 12288                  // Q -> FC1 hidden H
#define KB_OFF 24576
#define VB_OFF 36864
#define W0_OFF 49152                  // k-pair-interleaved weight, 4096 floats
#define W1_OFF 53248
#define SMEM_FLOATS 57344
#define SMEM_BYTES (SMEM_FLOATS * 4)  // 229376 B -> 1 CTA/SM

typedef unsigned long long ull;

__device__ __forceinline__ ull ffma2(ull a, ull b, ull c) {
    ull d;
    asm("fma.rn.f32x2 %0, %1, %2, %3;" : "=l"(d) : "l"(a), "l"(b), "l"(c));
    return d;
}
__device__ __forceinline__ float2 unpack2(ull v) {
    float2 r;
    asm("mov.b64 {%0, %1}, %2;" : "=f"(r.x), "=f"(r.y) : "l"(v));
    return r;
}

// XOR-swizzled row-major offset: buffers are 64 floats/row (16 chunks of 4);
// chunk index is XORed with (row>>3)&7 so rows 8/16/24 apart hit distinct banks.
__device__ __forceinline__ int swz4(int r, int k4) {  // k4 = k/4, k%4==0 accesses
    return r * DD + (((k4) ^ ((r >> 3) & 7)) << 2);
}

// ---------------------------------------------------------------------------
// Stage a 64x64 weight matrix in k-pair-interleaved form:
// Wp[p*128 + c*2 + {0,1}] = { W[2p][c], W[2p+1][c] }, p = 0..31.
// ---------------------------------------------------------------------------
__device__ __forceinline__ void load_weight_pairs(float* __restrict__ Wp,
                                                  const float* __restrict__ Wg,
                                                  int tid) {
#pragma unroll
    for (int it = 0; it < 2; ++it) {
        int idx = tid + it * NTHREADS;        // 512 tasks
        if (idx < 512) {
            int p = idx >> 4;
            int c = (idx & 15) * 4;
            float4 g0 = *(const float4*)(Wg + (2 * p) * DD + c);
            float4 g1 = *(const float4*)(Wg + (2 * p + 1) * DD + c);
            float* dst = Wp + p * 128 + c * 2;
            *(float4*)(dst)     = make_float4(g0.x, g1.x, g0.y, g1.y);
            *(float4*)(dst + 4) = make_float4(g0.z, g1.z, g0.w, g1.w);
        }
    }
}

// ---------------------------------------------------------------------------
// GEMM core: C[192x64] = A[192x64] @ W[64x64].
// A: swizzled row-major smem. W: k-pair-interleaved smem (Wp).
// Thread tile 8 rows x 4 cols; 24 row-groups x 16 col-groups = 384 threads.
// acc[i][j] packs {sum over even k, sum over odd k}; final = lo + hi.
// ---------------------------------------------------------------------------
__device__ __forceinline__ void gemm_core(const float* __restrict__ As,
                                          const float* __restrict__ Wp,
                                          ull acc[8][4], int r0, int c0) {
#pragma unroll
    for (int i = 0; i < 8; ++i)
#pragma unroll
        for (int j = 0; j < 4; ++j) acc[i][j] = 0ull;

#pragma unroll 2
    for (int kk = 0; kk < 64; kk += 4) {
        const int p0 = kk >> 1;               // k-pair rows p0, p0+1
        ulonglong2 wA = *(const ulonglong2*)(Wp + p0 * 128 + c0 * 2);
        ulonglong2 wB = *(const ulonglong2*)(Wp + p0 * 128 + (c0 + 2) * 2);
        ulonglong2 wC = *(const ulonglong2*)(Wp + (p0 + 1) * 128 + c0 * 2);
        ulonglong2 wD = *(const ulonglong2*)(Wp + (p0 + 1) * 128 + (c0 + 2) * 2);
#pragma unroll
        for (int i = 0; i < 8; ++i) {
            ulonglong2 a = *(const ulonglong2*)(As + swz4(r0 + i, kk >> 2));
            // a.x = {x[kk], x[kk+1]}, a.y = {x[kk+2], x[kk+3]}
            acc[i][0] = ffma2(a.x, wA.x, acc[i][0]);
            acc[i][1] = ffma2(a.x, wA.y, acc[i][1]);
            acc[i][2] = ffma2(a.x, wB.x, acc[i][2]);
            acc[i][3] = ffma2(a.x, wB.y, acc[i][3]);
            acc[i][0] = ffma2(a.y, wC.x, acc[i][0]);
            acc[i][1] = ffma2(a.y, wC.y, acc[i][1]);
            acc[i][2] = ffma2(a.y, wD.x, acc[i][2]);
            acc[i][3] = ffma2(a.y, wD.y, acc[i][3]);
        }
    }
}

// Epilogue -> swizzled smem buffer, bias + ReLU.
__device__ __forceinline__ void gemm_to_smem(const float* __restrict__ As,
                                             const float* __restrict__ Wp,
                                             const float* __restrict__ bias,
                                             float* __restrict__ outs, int tid) {
    const int r0 = (tid >> 4) * 8;
    const int c0 = (tid & 15) * 4;
    ull acc[8][4];
    gemm_core(As, Wp, acc, r0, c0);
    float4 bb = *(const float4*)(bias + c0);
#pragma unroll
    for (int i = 0; i < 8; ++i) {
        float2 p0 = unpack2(acc[i][0]);
        float2 p1 = unpack2(acc[i][1]);
        float2 p2 = unpack2(acc[i][2]);
        float2 p3 = unpack2(acc[i][3]);
        float4 r;
        r.x = fmaxf(p0.x + p0.y + bb.x, 0.f);
        r.y = fmaxf(p1.x + p1.y + bb.y, 0.f);
        r.z = fmaxf(p2.x + p2.y + bb.z, 0.f);
        r.w = fmaxf(p3.x + p3.y + bb.w, 0.f);
        *(float4*)(outs + swz4(r0 + i, c0 >> 2)) = r;
    }
}

// Epilogue -> global Y (final layer), bias, no ReLU, node guard.
__device__ __forceinline__ void gemm_to_global(const float* __restrict__ As,
                                               const float* __restrict__ Wp,
                                               const float* __restrict__ bias,
                                               float* __restrict__ Y,
                                               int b, int n0, int tid) {
    const int r0 = (tid >> 4) * 8;
    const int c0 = (tid & 15) * 4;
    ull acc[8][4];
    gemm_core(As, Wp, acc, r0, c0);
    float4 bb = *(const float4*)(bias + c0);
#pragma unroll
    for (int i = 0; i < 8; ++i) {
        int row = r0 + i;
        int node = row / TT;
        int t = row - node * TT;
        int n = n0 + node;
        if (n < NN) {
            float2 p0 = unpack2(acc[i][0]);
            float2 p1 = unpack2(acc[i][1]);
            float2 p2 = unpack2(acc[i][2]);
            float2 p3 = unpack2(acc[i][3]);
            float4 r = make_float4(p0.x + p0.y + bb.x, p1.x + p1.y + bb.y,
                                   p2.x + p2.y + bb.z, p3.x + p3.y + bb.w);
            *(float4*)(Y + ((size_t)(b * TT + t) * NN + n) * DD + c0) = r;
        }
    }
}

// ---------------------------------------------------------------------------
// Per-(node, t, head) attention over the temporal axis (keep s >= t).
// All buffers swizzled row-major. Writes O over the X buffer.
// ---------------------------------------------------------------------------
__device__ __forceinline__ void attention(const float* __restrict__ Qs,
                                          const float* __restrict__ Ks,
                                          const float* __restrict__ Vs,
                                          float* __restrict__ Os,
                                          int tid) {
    const float scale = 0.3535533905932738f;  // 1/sqrt(8)
#pragma unroll 1
    for (int iter = 0; iter < NB * TT * NHEAD / NTHREADS; ++iter) {
        int task = iter * NTHREADS + tid;     // 0..1535
        int h = task & 7;
        int t = (task >> 3) % TT;
        int node = task / (TT * NHEAD);
        int row_t = node * TT + t;
        int ch = 2 * h;                       // chunk index of head start

        float4 q0 = *(const float4*)(Qs + swz4(row_t, ch));
        float4 q1 = *(const float4*)(Qs + swz4(row_t, ch + 1));
        q0.x *= scale; q0.y *= scale; q0.z *= scale; q0.w *= scale;
        q1.x *= scale; q1.y *= scale; q1.z *= scale; q1.w *= scale;

        float p[TT];
        float m = -1e30f;
#pragma unroll
        for (int s = 0; s < TT; ++s) {
            int row_s = node * TT + s;
            float4 k0 = *(const float4*)(Ks + swz4(row_s, ch));
            float4 k1 = *(const float4*)(Ks + swz4(row_s, ch + 1));
            float dot = q0.x * k0.x;
            dot = fmaf(q0.y, k0.y, dot);
            dot = fmaf(q0.z, k0.z, dot);
            dot = fmaf(q0.w, k0.w, dot);
            dot = fmaf(q1.x, k1.x, dot);
            dot = fmaf(q1.y, k1.y, dot);
            dot = fmaf(q1.z, k1.z, dot);
            dot = fmaf(q1.w, k1.w, dot);
            dot = (s >= t) ? dot : -1e30f;
            p[s] = dot;
            m = fmaxf(m, dot);
        }
        float sum = 0.0f;
#pragma unroll
        for (int s = 0; s < TT; ++s) {
            float e = __expf(p[s] - m);   // masked -> exactly 0
            p[s] = e;
            sum += e;
        }
        float inv = 1.0f / sum;

        float o[8] = {0, 0, 0, 0, 0, 0, 0, 0};
#pragma unroll
        for (int s = 0; s < TT; ++s) {
            int row_s = node * TT + s;
            float4 v0 = *(const float4*)(Vs + swz4(row_s, ch));
            float4 v1 = *(const float4*)(Vs + swz4(row_s, ch + 1));
            o[0] = fmaf(p[s], v0.x, o[0]);
            o[1] = fmaf(p[s], v0.y, o[1]);
            o[2] = fmaf(p[s], v0.z, o[2]);
            o[3] = fmaf(p[s], v0.w, o[3]);
            o[4] = fmaf(p[s], v1.x, o[4]);
            o[5] = fmaf(p[s], v1.y, o[5]);
            o[6] = fmaf(p[s], v1.z, o[6]);
            o[7] = fmaf(p[s], v1.w, o[7]);
        }
        *(float4*)(Os + swz4(row_t, ch)) =
            make_float4(o[0] * inv, o[1] * inv, o[2] * inv, o[3] * inv);
        *(float4*)(Os + swz4(row_t, ch + 1)) =
            make_float4(o[4] * inv, o[5] * inv, o[6] * inv, o[7] * inv);
    }
}

// ---------------------------------------------------------------------------
// Fused kernel: one CTA per (batch, 8-node tile).
// ---------------------------------------------------------------------------
__global__ void __launch_bounds__(NTHREADS, 1)
temporal_attention_fused(const float* __restrict__ X,
                         const float* __restrict__ Wq, const float* __restrict__ bq,
                         const float* __restrict__ Wk, const float* __restrict__ bk,
                         const float* __restrict__ Wv, const float* __restrict__ bv,
                         const float* __restrict__ Wf1, const float* __restrict__ bf1,
                         const float* __restrict__ Wf2, const float* __restrict__ bf2,
                         float* __restrict__ Y) {
    extern __shared__ float smem[];
    float* Xb = smem + XB_OFF;   // X, later attention output O
    float* Qb = smem + QB_OFF;   // Q, later FC1 hidden H
    float* Kb = smem + KB_OFF;
    float* Vb = smem + VB_OFF;
    float* W0 = smem + W0_OFF;
    float* W1 = smem + W1_OFF;

    const int tid = threadIdx.x;
    const int n0 = blockIdx.x * NB;
    const int b = blockIdx.y;

    // Load X tile into swizzled layout; zero-fill out-of-range nodes.
#pragma unroll 2
    for (int i = tid; i < MROWS * 16; i += NTHREADS) {
        int row = i >> 4;
        int f4 = i & 15;
        int node = row / TT;
        int t = row - node * TT;
        int n = n0 + node;
        float4 v = make_float4(0.f, 0.f, 0.f, 0.f);
        if (n < NN)
            v = *(const float4*)(X + ((size_t)(b * TT + t) * NN + n) * DD + f4 * 4);
        *(float4*)(Xb + swz4(row, f4)) = v;
    }
    load_weight_pairs(W0, Wq, tid);
    __syncthreads();

    load_weight_pairs(W1, Wk, tid);           // overlap with Q GEMM
    gemm_to_smem(Xb, W0, bq, Qb, tid);        // q = relu(X@Wq + bq)
    __syncthreads();

    load_weight_pairs(W0, Wv, tid);
    gemm_to_smem(Xb, W1, bk, Kb, tid);        // k
    __syncthreads();

    load_weight_pairs(W1, Wf1, tid);
    gemm_to_smem(Xb, W0, bv, Vb, tid);        // v
    __syncthreads();

    attention(Qb, Kb, Vb, Xb, tid);           // O overwrites X buffer
    __syncthreads();

    load_weight_pairs(W0, Wf2, tid);
    gemm_to_smem(Xb, W1, bf1, Qb, tid);       // h = relu(O@Wf1 + bf1) -> Q buffer
    __syncthreads();

    gemm_to_global(Qb, W0, bf2, Y, b, n0, tid);  // y = h@Wf2 + bf2
}

// ---------------------------------------------------------------------------
// kernel_launch: inputs per metadata order:
// 0=X 1=STE(unused) 2=Wq 3=bq 4=Wk 5=bk 6=Wv 7=bv 8=Wf1 9=bf1 10=Wf2 11=bf2
// ---------------------------------------------------------------------------
extern "C" void kernel_launch(void* const* d_in, const int* in_sizes, int n_in,
                              void* d_out, int out_size) {
    const float* X   = (const float*)d_in[0];
    const float* Wq  = (const float*)d_in[2];
    const float* bq  = (const float*)d_in[3];
    const float* Wk  = (const float*)d_in[4];
    const float* bk  = (const float*)d_in[5];
    const float* Wv  = (const float*)d_in[6];
    const float* bv  = (const float*)d_in[7];
    const float* Wf1 = (const float*)d_in[8];
    const float* bf1 = (const float*)d_in[9];
    const float* Wf2 = (const float*)d_in[10];
    const float* bf2 = (const float*)d_in[11];
    float* Y = (float*)d_out;

    cudaFuncSetAttribute(temporal_attention_fused,
                         cudaFuncAttributeMaxDynamicSharedMemorySize, SMEM_BYTES);

    dim3 grid(NTILES, BB);
    temporal_attention_fused<<<grid, NTHREADS, SMEM_BYTES>>>(
        X, Wq, bq, Wk, bk, Wv, bv, Wf1, bf1, Wf2, bf2, Y);
}